// round 8
// baseline (speedup 1.0000x reference)
#include <cuda_runtime.h>

#define NN 50000
#define EE 800000

typedef unsigned long long u64;

// ---------------- f32x2 helpers ----------------
__device__ __forceinline__ void fma2(u64 &c, u64 a, u64 b){
    asm("fma.rn.f32x2 %0, %1, %2, %0;" : "+l"(c) : "l"(a), "l"(b));
}
__device__ __forceinline__ u64 pack2(float x, float y){
    u64 r; asm("mov.b64 %0, {%1, %2};" : "=l"(r) : "f"(x), "f"(y)); return r;
}
__device__ __forceinline__ float2 unpack2(u64 v){
    float2 r; asm("mov.b64 {%0, %1}, %2;" : "=f"(r.x), "=f"(r.y) : "l"(v)); return r;
}
__device__ __forceinline__ float sigf(float x){ return 1.f/(1.f+__expf(-x)); }

// ---------------- scratch ----------------
__device__ float g_node_pre[(size_t)NN*64];
__device__ float g_nf_logit[(size_t)NN*3];
__device__ float g_prevp[NN];
__device__ float g_agg[(size_t)NN*64];
__device__ float g_contrib[(size_t)EE*64];
__device__ float g_message[(size_t)EE*64];
__device__ float g_m[(size_t)EE*64];
__device__ float g_x[(size_t)EE*64];
__device__ float g_gi[(size_t)EE*192];   // 3 planes of [EE][64]
__device__ float g_gh[(size_t)EE*192];
__device__ int   g_deg[NN];
__device__ int   g_rowptr[NN+1];
__device__ int   g_cursor[NN];
__device__ int   g_eid[EE];

// smem budgets (floats):
//  k_me/k_mp/edge_init: Xs 64*65 (4160, doubles as Os) + Ws 4096 + bs 64 = 8320 -> 33280 B -> 6 blocks/SM
//  k_gate:              Xs 4160 + Os 4160 + Ws 4096 + bs 64 = 12480 -> 49920 B -> 4 blocks/SM
#define DSM_A 33280
#define DSM_B 49920

// ---------------- GEMM core: TE=64; warp w -> cols 16w..16w+15; lane -> edges lane+32j ----------------
// W stride 64 (broadcast loads never conflict). X stride 65 (conflict-free per-lane rows).
template<int NJ>
__device__ __forceinline__ void gemm_core(const float* Xs, const float* Ws, const float* bs,
                                          int w, int lane, u64 (&acc)[NJ][8])
{
    const int c0 = w*16;
    #pragma unroll
    for (int j=0;j<NJ;j++)
        #pragma unroll
        for (int q=0;q<8;q++) acc[j][q]=pack2(bs[c0+2*q],bs[c0+2*q+1]);
    #pragma unroll 4
    for (int k=0;k<64;k++){
        const ulonglong2* wp=(const ulonglong2*)(Ws + k*64 + c0);
        ulonglong2 a0=wp[0],a1=wp[1],a2=wp[2],a3=wp[3];
        u64 w8[8]={a0.x,a0.y,a1.x,a1.y,a2.x,a2.y,a3.x,a3.y};
        #pragma unroll
        for (int j=0;j<NJ;j++){
            float xk = Xs[(lane+32*j)*65 + k];
            u64 x2 = pack2(xk,xk);
            #pragma unroll
            for (int q=0;q<8;q++) fma2(acc[j][q],x2,w8[q]);
        }
    }
}
template<int NJ>
__device__ __forceinline__ void acc_to_os(float* Os,int w,int lane,u64 (&acc)[NJ][8]){
    const int c0=w*16;
    #pragma unroll
    for (int j=0;j<NJ;j++){
        float* row=&Os[(lane+32*j)*65 + c0];
        #pragma unroll
        for (int q=0;q<8;q++){ float2 v=unpack2(acc[j][q]); row[2*q]=v.x; row[2*q+1]=v.y; }
    }
}

// ---------------- CSR build ----------------
__global__ void __launch_bounds__(256) k_hist(const int* __restrict__ tgt){
    int e=blockIdx.x*256+threadIdx.x;
    atomicAdd(&g_deg[tgt[e]],1);
}
__global__ void __launch_bounds__(1024) k_scan(){
    __shared__ int wsum[32];
    __shared__ int carry_s;
    int t=threadIdx.x, lane=t&31, wid=t>>5;
    if (t==0){ g_rowptr[0]=0; carry_s=0; }
    __syncthreads();
    for (int base=0; base<NN; base+=1024){
        int i=base+t;
        int v=(i<NN)? g_deg[i] : 0;
        int s=v;
        #pragma unroll
        for (int o=1;o<32;o<<=1){ int u=__shfl_up_sync(0xffffffffu,s,o); if(lane>=o) s+=u; }
        if (lane==31) wsum[wid]=s;
        __syncthreads();
        if (wid==0){
            int ws=wsum[lane];
            #pragma unroll
            for (int o=1;o<32;o<<=1){ int u=__shfl_up_sync(0xffffffffu,ws,o); if(lane>=o) ws+=u; }
            wsum[lane]=ws;
        }
        __syncthreads();
        int off=(wid>0)? wsum[wid-1] : 0;
        int inc=s+off+carry_s;
        if (i<NN){ g_rowptr[i+1]=inc; g_cursor[i]=inc-v; }
        __syncthreads();
        if (t==1023) carry_s=inc;
        __syncthreads();
    }
}
__global__ void __launch_bounds__(256) k_fill(const int* __restrict__ tgt){
    int e=blockIdx.x*256+threadIdx.x;
    int p=atomicAdd(&g_cursor[tgt[e]],1);
    g_eid[p]=e;
}

// ---------------- segment sum by gather ----------------
__global__ void __launch_bounds__(256) k_gather(const float* __restrict__ S){
    int node=blockIdx.x*4+(threadIdx.x>>6);
    int f=threadIdx.x&63;
    int s=g_rowptr[node], e=g_rowptr[node+1];
    float a=0.f;
    for (int i=s;i<e;i++){
        int eid=__ldg(&g_eid[i]);
        a += __ldg(&S[(size_t)eid*64+f]);
    }
    g_agg[(size_t)node*64+f]=a;
}

// ---------------- per-node precompute ----------------
__global__ void __launch_bounds__(256) k_node(
    const float* __restrict__ prob, const float* __restrict__ seed,
    const float* __restrict__ W_node, const float* __restrict__ b_node,
    const float* __restrict__ W_init, const float* __restrict__ b_init,
    const float* __restrict__ W_out,  const float* __restrict__ b_out)
{
    __shared__ float Wi[4096];
    __shared__ float Wn0[64], Wn1[64], bn[64], bi[64], Wo[192], bo[3];
    int tid = threadIdx.x;
    for (int i=tid;i<4096;i+=256) Wi[i]=W_init[i];
    if (tid<64){ Wn0[tid]=W_node[tid]; Wn1[tid]=W_node[64+tid]; bn[tid]=b_node[tid]; bi[tid]=b_init[tid]; }
    for (int i=tid;i<192;i+=256) Wo[i]=W_out[192+i];
    if (tid<3) bo[tid]=b_out[tid];
    __syncthreads();
    int n = blockIdx.x*256 + tid;
    if (n >= NN) return;
    float p = prob[n], s = seed[n];
    u64 acc[32];
    #pragma unroll
    for (int j=0;j<32;j++) acc[j]=pack2(bi[2*j],bi[2*j+1]);
    float l0=bo[0], l1=bo[1], l2=bo[2];
    #pragma unroll 4
    for (int k=0;k<64;k++){
        float nf = fmaxf(fmaf(p,Wn0[k],fmaf(s,Wn1[k],bn[k])), 0.f);
        u64 x2 = pack2(nf,nf);
        const ulonglong2* wr = (const ulonglong2*)&Wi[k*64];
        #pragma unroll
        for (int q=0;q<16;q++){ ulonglong2 w=wr[q]; fma2(acc[2*q],x2,w.x); fma2(acc[2*q+1],x2,w.y); }
        l0 = fmaf(nf,Wo[k*3],l0); l1 = fmaf(nf,Wo[k*3+1],l1); l2 = fmaf(nf,Wo[k*3+2],l2);
    }
    float4* outp = (float4*)&g_node_pre[(size_t)n*64];
    #pragma unroll
    for (int q=0;q<16;q++){ float2 a=unpack2(acc[2*q]); float2 b=unpack2(acc[2*q+1]); outp[q]=make_float4(a.x,a.y,b.x,b.y); }
    g_nf_logit[n*3]=l0; g_nf_logit[n*3+1]=l1; g_nf_logit[n*3+2]=l2;
}

// ---------------- edge init: message + contrib (TE=64, NJ=2) ----------------
__global__ void __launch_bounds__(128,6) k_edge_init(
    const float* __restrict__ raw, const int* __restrict__ src,
    const float* __restrict__ W_edge, const float* __restrict__ b_edge,
    const float* __restrict__ W_init, const float* __restrict__ W_me)
{
    extern __shared__ float sm[];
    float* Xs=sm; float* Ws=sm+4160; float* bs=Ws+4096;
    __shared__ float we[64], be[64], rawv[64];
    __shared__ int srcs[64];
    int tid=threadIdx.x, w=tid>>5, lane=tid&31;
    size_t base=(size_t)blockIdx.x*64;
    if (tid<64){ we[tid]=W_edge[tid]; be[tid]=b_edge[tid]; bs[tid]=0.f;
                 rawv[tid]=raw[base+tid]; srcs[tid]=src[base+tid]; }
    for (int i=tid;i<4096;i+=128) Ws[i]=W_init[4096+i];
    __syncthreads();
    for (int i=tid;i<4096;i+=128){ int e=i>>6,f=i&63; Xs[e*65+f]=fmaxf(fmaf(rawv[e],we[f],be[f]),0.f); }
    __syncthreads();
    u64 acc[2][8];
    gemm_core<2>(Xs,Ws,bs,w,lane,acc);
    __syncthreads();
    acc_to_os<2>(Xs,w,lane,acc);
    __syncthreads();
    for (int i=tid;i<4096;i+=128){
        int e=i>>6, f=i&63;
        float v=Xs[e*65+f] + __ldg(&g_node_pre[(size_t)srcs[e]*64+f]);
        g_message[base*64+i]=fmaxf(v,0.f);
    }
    __syncthreads();
    // pass 2: contrib = ef @ W_me[64:128]
    for (int i=tid;i<4096;i+=128) Ws[i]=W_me[4096+i];
    __syncthreads();
    for (int i=tid;i<4096;i+=128){ int e=i>>6,f=i&63; Xs[e*65+f]=fmaxf(fmaf(rawv[e],we[f],be[f]),0.f); }
    __syncthreads();
    gemm_core<2>(Xs,Ws,bs,w,lane,acc);
    __syncthreads();
    acc_to_os<2>(Xs,w,lane,acc);
    __syncthreads();
    for (int i=tid;i<4096;i+=128) g_contrib[base*64+i]=Xs[(i>>6)*65+(i&63)];
}

// ---------------- m = relu(message @ W_me[0:64] + contrib + b_me) ----------------
__global__ void __launch_bounds__(128,6) k_me(const float* __restrict__ W, const float* __restrict__ b)
{
    extern __shared__ float sm[];
    float* Xs=sm; float* Ws=sm+4160; float* bs=Ws+4096;
    int tid=threadIdx.x, w=tid>>5, lane=tid&31;
    size_t base=(size_t)blockIdx.x*64;
    for (int i=tid;i<4096;i+=128) Ws[i]=W[i];
    if (tid<64) bs[tid]=b[tid];
    for (int i=tid;i<4096;i+=128) Xs[(i>>6)*65+(i&63)]=g_message[base*64+i];
    __syncthreads();
    u64 acc[2][8];
    gemm_core<2>(Xs,Ws,bs,w,lane,acc);
    __syncthreads();
    acc_to_os<2>(Xs,w,lane,acc);
    __syncthreads();
    for (int i=tid;i<4096;i+=128){
        float v=Xs[(i>>6)*65+(i&63)] + g_contrib[base*64+i];
        g_m[base*64+i]=fmaxf(v,0.f);
    }
}

// ---------------- x = relu((agg[src] - m[rev]) @ W_mp + b_mp) ----------------
__global__ void __launch_bounds__(128,6) k_mp(
    const float* __restrict__ W, const float* __restrict__ b,
    const int* __restrict__ src, const int* __restrict__ rev)
{
    extern __shared__ float sm[];
    float* Xs=sm; float* Ws=sm+4160; float* bs=Ws+4096;
    __shared__ int srcs[64], revs[64];
    int tid=threadIdx.x, w=tid>>5, lane=tid&31;
    size_t base=(size_t)blockIdx.x*64;
    if (tid<64){ srcs[tid]=src[base+tid]; revs[tid]=rev[base+tid]; }
    for (int i=tid;i<4096;i+=128) Ws[i]=W[i];
    if (tid<64) bs[tid]=b[tid];
    __syncthreads();
    for (int i=tid;i<4096;i+=128){
        int e=i>>6, f=i&63;
        Xs[e*65+f] = __ldg(&g_agg[(size_t)srcs[e]*64+f]) - __ldg(&g_m[(size_t)revs[e]*64+f]);
    }
    __syncthreads();
    u64 acc[2][8];
    gemm_core<2>(Xs,Ws,bs,w,lane,acc);
    __syncthreads();
    acc_to_os<2>(Xs,w,lane,acc);
    __syncthreads();
    for (int i=tid;i<4096;i+=128) g_x[base*64+i]=fmaxf(Xs[(i>>6)*65+(i&63)],0.f);
}

// ---------------- gates: TE=64, NJ=2, 3 gb passes, X kept live across passes ----------------
__global__ void __launch_bounds__(128,4) k_gate(
    const float* __restrict__ Wg, const float* __restrict__ bg,
    const float* __restrict__ Xg, float* __restrict__ Og)
{
    extern __shared__ float sm[];
    float* Xs=sm;            // 64*65
    float* Os=sm+4160;       // 64*65
    float* Ws=sm+8320;       // 64*64
    float* bs=Ws+4096;
    int tid=threadIdx.x, w=tid>>5, lane=tid&31;
    size_t base=(size_t)blockIdx.x*64;
    for (int i=tid;i<4096;i+=128) Xs[(i>>6)*65+(i&63)]=Xg[base*64+i];
    for (int gb=0; gb<3; gb++){
        __syncthreads();
        for (int i=tid;i<4096;i+=128){ int c=i>>6, k=i&63; Ws[k*64+c]=Wg[gb*4096+i]; }
        if (tid<64) bs[tid]=bg[gb*64+tid];
        __syncthreads();
        u64 acc[2][8];
        gemm_core<2>(Xs,Ws,bs,w,lane,acc);
        acc_to_os<2>(Os,w,lane,acc);
        __syncthreads();
        float* outp = Og + (size_t)gb*((size_t)EE*64) + base*64;
        for (int i=tid;i<4096;i+=128) outp[i]=Os[(i>>6)*65+(i&63)];
    }
}

// ---------------- GRU elementwise (float4, plane layout) ----------------
__global__ void __launch_bounds__(256) k_gru(){
    size_t idx=((size_t)blockIdx.x*256+threadIdx.x)*4;
    const size_t P=(size_t)EE*64;
    float4 ir=*(const float4*)&g_gi[idx];
    float4 iz=*(const float4*)&g_gi[P+idx];
    float4 in4=*(const float4*)&g_gi[2*P+idx];
    float4 hr=*(const float4*)&g_gh[idx];
    float4 hz=*(const float4*)&g_gh[P+idx];
    float4 hn=*(const float4*)&g_gh[2*P+idx];
    float4 h=*(const float4*)&g_message[idx];
    float4 o;
    {
        float r=sigf(ir.x+hr.x), z=sigf(iz.x+hz.x);
        float n=2.f*sigf(2.f*(in4.x+r*hn.x))-1.f;
        o.x=(1.f-z)*n+z*h.x;
    }{
        float r=sigf(ir.y+hr.y), z=sigf(iz.y+hz.y);
        float n=2.f*sigf(2.f*(in4.y+r*hn.y))-1.f;
        o.y=(1.f-z)*n+z*h.y;
    }{
        float r=sigf(ir.z+hr.z), z=sigf(iz.z+hz.z);
        float n=2.f*sigf(2.f*(in4.z+r*hn.z))-1.f;
        o.z=(1.f-z)*n+z*h.z;
    }{
        float r=sigf(ir.w+hr.w), z=sigf(iz.w+hz.w);
        float n=2.f*sigf(2.f*(in4.w+r*hn.w))-1.f;
        o.w=(1.f-z)*n+z*h.w;
    }
    *(float4*)&g_message[idx]=o;
}

// ---------------- nodes_out ----------------
__global__ void __launch_bounds__(256) k_nodes_out(
    int iter, float* __restrict__ outM, float* __restrict__ outD,
    const float* __restrict__ Wagg, const float* __restrict__ bagg,
    const float* __restrict__ Wout)
{
    __shared__ float Wa[4096]; __shared__ float ba[64]; __shared__ float Wo[192];
    int tid=threadIdx.x;
    for (int i=tid;i<4096;i+=256) Wa[i]=Wagg[i];
    if (tid<64) ba[tid]=bagg[tid];
    for (int i=tid;i<192;i+=256) Wo[i]=Wout[i];
    __syncthreads();
    int n=blockIdx.x*256+tid;
    if (n>=NN) return;
    float af[64];
    const float4* ar=(const float4*)&g_agg[(size_t)n*64];
    #pragma unroll
    for (int q=0;q<16;q++){ float4 v=ar[q]; af[4*q]=v.x; af[4*q+1]=v.y; af[4*q+2]=v.z; af[4*q+3]=v.w; }
    u64 acc[32];
    #pragma unroll
    for (int j=0;j<32;j++) acc[j]=pack2(ba[2*j],ba[2*j+1]);
    #pragma unroll 4
    for (int k=0;k<64;k++){
        u64 x2=pack2(af[k],af[k]);
        const ulonglong2* wr=(const ulonglong2*)&Wa[k*64];
        #pragma unroll
        for (int q=0;q<16;q++){ ulonglong2 w=wr[q]; fma2(acc[2*q],x2,w.x); fma2(acc[2*q+1],x2,w.y); }
    }
    float l0=0.f,l1=0.f,l2=0.f;
    #pragma unroll
    for (int j=0;j<32;j++){
        float2 v=unpack2(acc[j]);
        float a0=fmaxf(v.x,0.f), a1=fmaxf(v.y,0.f);
        int k0=2*j, k1=2*j+1;
        l0 += a0*Wo[k0*3+0] + a1*Wo[k1*3+0];
        l1 += a0*Wo[k0*3+1] + a1*Wo[k1*3+1];
        l2 += a0*Wo[k0*3+2] + a1*Wo[k1*3+2];
    }
    l0=fmaxf(l0+g_nf_logit[n*3+0],0.f);
    l1=fmaxf(l1+g_nf_logit[n*3+1],0.f);
    l2=fmaxf(l2+g_nf_logit[n*3+2],0.f);
    float mx=fmaxf(l0,fmaxf(l1,l2));
    float e0=expf(l0-mx), e1=expf(l1-mx), e2=expf(l2-mx);
    float sum=e0+e1+e2, ls=logf(sum);
    size_t ob=(size_t)iter*((size_t)NN*3)+(size_t)n*3;
    outM[ob+0]=l0-mx-ls; outM[ob+1]=l1-mx-ls; outM[ob+2]=l2-mx-ls;
    float p2=e2/sum;
    if (iter>0){
        float d=fabsf(p2-g_prevp[n]);
        atomicMax((int*)&outD[iter-1], __float_as_int(d));
    }
    g_prevp[n]=p2;
}

// ---------------- host ----------------
extern "C" void kernel_launch(void* const* d_in, const int* in_sizes, int n_in,
                              void* d_out, int out_size)
{
    const int*   src  = (const int*)  d_in[0];
    const int*   tgt  = (const int*)  d_in[1];
    const int*   rev  = (const int*)  d_in[2];
    const float* raw  = (const float*)d_in[3];
    const float* prob = (const float*)d_in[4];
    const float* seed = (const float*)d_in[5];
    const float* W_node=(const float*)d_in[6],  *b_node=(const float*)d_in[7];
    const float* W_edge=(const float*)d_in[8],  *b_edge=(const float*)d_in[9];
    const float* W_init=(const float*)d_in[10], *b_init=(const float*)d_in[11];
    const float* W_aggr=(const float*)d_in[12], *b_aggr=(const float*)d_in[13];
    const float* W_out =(const float*)d_in[14], *b_out =(const float*)d_in[15];
    const float* W_me  =(const float*)d_in[16], *b_me  =(const float*)d_in[17];
    const float* W_mp  =(const float*)d_in[18], *b_mp  =(const float*)d_in[19];
    const float* W_ih  =(const float*)d_in[20], *W_hh  =(const float*)d_in[21];
    const float* b_ih  =(const float*)d_in[22], *b_hh  =(const float*)d_in[23];

    float* outM = (float*)d_out;
    float* outD = (float*)d_out + (size_t)5*NN*3;

    cudaFuncSetAttribute(k_edge_init, cudaFuncAttributeMaxDynamicSharedMemorySize, DSM_A);
    cudaFuncSetAttribute(k_me,        cudaFuncAttributeMaxDynamicSharedMemorySize, DSM_A);
    cudaFuncSetAttribute(k_mp,        cudaFuncAttributeMaxDynamicSharedMemorySize, DSM_A);
    cudaFuncSetAttribute(k_gate,      cudaFuncAttributeMaxDynamicSharedMemorySize, DSM_B);

    void *degPtr=0, *msgPtr=0, *mPtr=0, *xPtr=0, *giPtr=0, *ghPtr=0;
    cudaGetSymbolAddress(&degPtr, g_deg);
    cudaGetSymbolAddress(&msgPtr, g_message);
    cudaGetSymbolAddress(&mPtr,   g_m);
    cudaGetSymbolAddress(&xPtr,   g_x);
    cudaGetSymbolAddress(&giPtr,  g_gi);
    cudaGetSymbolAddress(&ghPtr,  g_gh);

    cudaMemsetAsync(degPtr, 0, NN*sizeof(int));
    cudaMemsetAsync(outD, 0, 4*sizeof(float));

    k_hist<<<EE/256,256>>>(tgt);
    k_scan<<<1,1024>>>();
    k_fill<<<EE/256,256>>>(tgt);
    k_node<<<(NN+255)/256,256>>>(prob, seed, W_node, b_node, W_init, b_init, W_out, b_out);
    k_edge_init<<<EE/64,128,DSM_A>>>(raw, src, W_edge, b_edge, W_init, W_me);

    k_gather<<<NN/4,256>>>((const float*)msgPtr);
    k_nodes_out<<<(NN+255)/256,256>>>(0, outM, outD, W_aggr, b_aggr, W_out);

    for (int l=0; l<4; l++){
        k_me<<<EE/64,128,DSM_A>>>(W_me, b_me);
        k_gather<<<NN/4,256>>>((const float*)mPtr);
        k_mp<<<EE/64,128,DSM_A>>>(W_mp, b_mp, src, rev);
        k_gate<<<EE/64,128,DSM_B>>>(W_ih, b_ih, (const float*)xPtr, (float*)giPtr);
        k_gate<<<EE/64,128,DSM_B>>>(W_hh, b_hh, (const float*)msgPtr, (float*)ghPtr);
        k_gru<<<(EE*64/4)/256,256>>>();
        k_gather<<<NN/4,256>>>((const float*)msgPtr);
        k_nodes_out<<<(NN+255)/256,256>>>(l+1, outM, outD, W_aggr, b_aggr, W_out);
    }
}

// round 10
// speedup vs baseline: 1.8627x; 1.8627x over previous
#include <cuda_runtime.h>

#define NN 50000
#define EE 800000

typedef unsigned long long u64;

// ---------------- f32x2 helpers ----------------
__device__ __forceinline__ void fma2(u64 &c, u64 a, u64 b){
    asm("fma.rn.f32x2 %0, %1, %2, %0;" : "+l"(c) : "l"(a), "l"(b));
}
__device__ __forceinline__ u64 pack2(float x, float y){
    u64 r; asm("mov.b64 %0, {%1, %2};" : "=l"(r) : "f"(x), "f"(y)); return r;
}
__device__ __forceinline__ float2 unpack2(u64 v){
    float2 r; asm("mov.b64 {%0, %1}, %2;" : "=f"(r.x), "=f"(r.y) : "l"(v)); return r;
}
__device__ __forceinline__ float sigf(float x){ return 1.f/(1.f+__expf(-x)); }

// ---------------- scratch ----------------
__device__ float g_node_pre[(size_t)NN*64];
__device__ float g_nf_logit[(size_t)NN*3];
__device__ float g_prevp[NN];
__device__ float g_agg[(size_t)NN*64];
__device__ float g_contrib[(size_t)EE*64];
__device__ float g_message[(size_t)EE*64];
__device__ float g_m[(size_t)EE*64];
__device__ float g_x[(size_t)EE*64];
__device__ int   g_deg[NN];
__device__ int   g_rowptr[NN+1];
__device__ int   g_cursor[NN];
__device__ int   g_eid[EE];

#define DSM 50944            // gemm kernels: Xs 8320 + Ws 4352 + bs 64 floats
#define DSM_GRU 204800       // fused gru: Xs 8320 + Hs 8320 + W 26112 + Zs 8192 + b 256 floats
#define GRU_GRID 152
#define GRU_TILES 6250       // EE/128

// ---------------- GEMM core: TE=128; warp w -> cols 16w..; lane -> edges lane+32j ----------------
template<int NJ>
__device__ __forceinline__ void gemm_core(const float* Xs, const float* Ws, const float* bs,
                                          int w, int lane, u64 (&acc)[NJ][8])
{
    const int c0 = w*16;
    #pragma unroll
    for (int j=0;j<NJ;j++)
        #pragma unroll
        for (int q=0;q<8;q++) acc[j][q]=pack2(bs[c0+2*q],bs[c0+2*q+1]);
    #pragma unroll 2
    for (int k=0;k<64;k++){
        const ulonglong2* wp=(const ulonglong2*)(Ws + k*68 + c0);
        ulonglong2 a0=wp[0],a1=wp[1],a2=wp[2],a3=wp[3];
        u64 w8[8]={a0.x,a0.y,a1.x,a1.y,a2.x,a2.y,a3.x,a3.y};
        #pragma unroll
        for (int j=0;j<NJ;j++){
            float xk = Xs[(lane+32*j)*65 + k];
            u64 x2 = pack2(xk,xk);
            #pragma unroll
            for (int q=0;q<8;q++) fma2(acc[j][q],x2,w8[q]);
        }
    }
}
template<int NJ>
__device__ __forceinline__ void acc_to_os(float* Os,int w,int lane,u64 (&acc)[NJ][8]){
    const int c0=w*16;
    #pragma unroll
    for (int j=0;j<NJ;j++){
        float* row=&Os[(lane+32*j)*65 + c0];
        #pragma unroll
        for (int q=0;q<8;q++){ float2 v=unpack2(acc[j][q]); row[2*q]=v.x; row[2*q+1]=v.y; }
    }
}

// ---------------- 8-col GEMM core for fused GRU ----------------
__device__ __forceinline__ void gemm8(const float* Xs, const float* Wm, int c0, int lane,
                                      u64 (&acc)[4][4])
{
    #pragma unroll 4
    for (int k=0;k<64;k++){
        const ulonglong2* wp=(const ulonglong2*)(Wm + k*68 + c0);
        ulonglong2 a0=wp[0], a1=wp[1];
        u64 w4[4]={a0.x,a0.y,a1.x,a1.y};
        #pragma unroll
        for (int j=0;j<4;j++){
            float xk = Xs[(lane+32*j)*65 + k];
            u64 x2 = pack2(xk,xk);
            #pragma unroll
            for (int q=0;q<4;q++) fma2(acc[j][q],x2,w4[q]);
        }
    }
}

// ---------------- CSR build ----------------
__global__ void __launch_bounds__(256) k_hist(const int* __restrict__ tgt){
    int e=blockIdx.x*256+threadIdx.x;
    atomicAdd(&g_deg[tgt[e]],1);
}
__global__ void __launch_bounds__(1024) k_scan(){
    __shared__ int wsum[32];
    __shared__ int carry_s;
    int t=threadIdx.x, lane=t&31, wid=t>>5;
    if (t==0){ g_rowptr[0]=0; carry_s=0; }
    __syncthreads();
    for (int base=0; base<NN; base+=1024){
        int i=base+t;
        int v=(i<NN)? g_deg[i] : 0;
        int s=v;
        #pragma unroll
        for (int o=1;o<32;o<<=1){ int u=__shfl_up_sync(0xffffffffu,s,o); if(lane>=o) s+=u; }
        if (lane==31) wsum[wid]=s;
        __syncthreads();
        if (wid==0){
            int ws=wsum[lane];
            #pragma unroll
            for (int o=1;o<32;o<<=1){ int u=__shfl_up_sync(0xffffffffu,ws,o); if(lane>=o) ws+=u; }
            wsum[lane]=ws;
        }
        __syncthreads();
        int off=(wid>0)? wsum[wid-1] : 0;
        int inc=s+off+carry_s;
        if (i<NN){ g_rowptr[i+1]=inc; g_cursor[i]=inc-v; }
        __syncthreads();
        if (t==1023) carry_s=inc;
        __syncthreads();
    }
}
__global__ void __launch_bounds__(256) k_fill(const int* __restrict__ tgt){
    int e=blockIdx.x*256+threadIdx.x;
    int p=atomicAdd(&g_cursor[tgt[e]],1);
    g_eid[p]=e;
}

// ---------------- segment sum by gather ----------------
__global__ void __launch_bounds__(256) k_gather(const float* __restrict__ S){
    int node=blockIdx.x*4+(threadIdx.x>>6);
    int f=threadIdx.x&63;
    int s=g_rowptr[node], e=g_rowptr[node+1];
    float a=0.f;
    for (int i=s;i<e;i++){
        int eid=__ldg(&g_eid[i]);
        a += __ldg(&S[(size_t)eid*64+f]);
    }
    g_agg[(size_t)node*64+f]=a;
}

// ---------------- per-node precompute ----------------
__global__ void __launch_bounds__(256) k_node(
    const float* __restrict__ prob, const float* __restrict__ seed,
    const float* __restrict__ W_node, const float* __restrict__ b_node,
    const float* __restrict__ W_init, const float* __restrict__ b_init,
    const float* __restrict__ W_out,  const float* __restrict__ b_out)
{
    __shared__ float Wi[4096];
    __shared__ float Wn0[64], Wn1[64], bn[64], bi[64], Wo[192], bo[3];
    int tid = threadIdx.x;
    for (int i=tid;i<4096;i+=256) Wi[i]=W_init[i];
    if (tid<64){ Wn0[tid]=W_node[tid]; Wn1[tid]=W_node[64+tid]; bn[tid]=b_node[tid]; bi[tid]=b_init[tid]; }
    for (int i=tid;i<192;i+=256) Wo[i]=W_out[192+i];
    if (tid<3) bo[tid]=b_out[tid];
    __syncthreads();
    int n = blockIdx.x*256 + tid;
    if (n >= NN) return;
    float p = prob[n], s = seed[n];
    u64 acc[32];
    #pragma unroll
    for (int j=0;j<32;j++) acc[j]=pack2(bi[2*j],bi[2*j+1]);
    float l0=bo[0], l1=bo[1], l2=bo[2];
    #pragma unroll 4
    for (int k=0;k<64;k++){
        float nf = fmaxf(fmaf(p,Wn0[k],fmaf(s,Wn1[k],bn[k])), 0.f);
        u64 x2 = pack2(nf,nf);
        const ulonglong2* wr = (const ulonglong2*)&Wi[k*64];
        #pragma unroll
        for (int q=0;q<16;q++){ ulonglong2 w=wr[q]; fma2(acc[2*q],x2,w.x); fma2(acc[2*q+1],x2,w.y); }
        l0 = fmaf(nf,Wo[k*3],l0); l1 = fmaf(nf,Wo[k*3+1],l1); l2 = fmaf(nf,Wo[k*3+2],l2);
    }
    float4* outp = (float4*)&g_node_pre[(size_t)n*64];
    #pragma unroll
    for (int q=0;q<16;q++){ float2 a=unpack2(acc[2*q]); float2 b=unpack2(acc[2*q+1]); outp[q]=make_float4(a.x,a.y,b.x,b.y); }
    g_nf_logit[n*3]=l0; g_nf_logit[n*3+1]=l1; g_nf_logit[n*3+2]=l2;
}

// ---------------- edge init (TE=128, NJ=4) ----------------
__global__ void __launch_bounds__(128,3) k_edge_init(
    const float* __restrict__ raw, const int* __restrict__ src,
    const float* __restrict__ W_edge, const float* __restrict__ b_edge,
    const float* __restrict__ W_init, const float* __restrict__ W_me)
{
    extern __shared__ float sm[];
    float* Xs=sm; float* Ws=sm+8320; float* bs=Ws+4352;
    __shared__ float we[64], be[64], rawv[128];
    __shared__ int srcs[128];
    int tid=threadIdx.x, w=tid>>5, lane=tid&31;
    size_t base=(size_t)blockIdx.x*128;
    if (tid<64){ we[tid]=W_edge[tid]; be[tid]=b_edge[tid]; bs[tid]=0.f; }
    rawv[tid]=raw[base+tid]; srcs[tid]=src[base+tid];
    for (int i=tid;i<4096;i+=128) Ws[(i>>6)*68+(i&63)]=W_init[4096+i];
    __syncthreads();
    for (int i=tid;i<8192;i+=128){ int e=i>>6,f=i&63; Xs[e*65+f]=fmaxf(fmaf(rawv[e],we[f],be[f]),0.f); }
    __syncthreads();
    u64 acc[4][8];
    gemm_core<4>(Xs,Ws,bs,w,lane,acc);
    __syncthreads();
    acc_to_os<4>(Xs,w,lane,acc);
    __syncthreads();
    for (int i=tid;i<8192;i+=128){
        int e=i>>6, f=i&63;
        float v=Xs[e*65+f] + __ldg(&g_node_pre[(size_t)srcs[e]*64+f]);
        g_message[base*64+i]=fmaxf(v,0.f);
    }
    __syncthreads();
    for (int i=tid;i<4096;i+=128) Ws[(i>>6)*68+(i&63)]=W_me[4096+i];
    __syncthreads();
    for (int i=tid;i<8192;i+=128){ int e=i>>6,f=i&63; Xs[e*65+f]=fmaxf(fmaf(rawv[e],we[f],be[f]),0.f); }
    __syncthreads();
    gemm_core<4>(Xs,Ws,bs,w,lane,acc);
    __syncthreads();
    acc_to_os<4>(Xs,w,lane,acc);
    __syncthreads();
    for (int i=tid;i<8192;i+=128) g_contrib[base*64+i]=Xs[(i>>6)*65+(i&63)];
}

// ---------------- m = relu(message @ W_me[0:64] + contrib + b_me) ----------------
__global__ void __launch_bounds__(128,3) k_me(const float* __restrict__ W, const float* __restrict__ b)
{
    extern __shared__ float sm[];
    float* Xs=sm; float* Ws=sm+8320; float* bs=Ws+4352;
    int tid=threadIdx.x, w=tid>>5, lane=tid&31;
    size_t base=(size_t)blockIdx.x*128;
    for (int i=tid;i<4096;i+=128) Ws[(i>>6)*68+(i&63)]=W[i];
    if (tid<64) bs[tid]=b[tid];
    for (int i=tid;i<8192;i+=128) Xs[(i>>6)*65+(i&63)]=g_message[base*64+i];
    __syncthreads();
    u64 acc[4][8];
    gemm_core<4>(Xs,Ws,bs,w,lane,acc);
    __syncthreads();
    acc_to_os<4>(Xs,w,lane,acc);
    __syncthreads();
    for (int i=tid;i<8192;i+=128){
        float v=Xs[(i>>6)*65+(i&63)] + g_contrib[base*64+i];
        g_m[base*64+i]=fmaxf(v,0.f);
    }
}

// ---------------- x = relu((agg[src] - m[rev]) @ W_mp + b_mp) ----------------
__global__ void __launch_bounds__(128,3) k_mp(
    const float* __restrict__ W, const float* __restrict__ b,
    const int* __restrict__ src, const int* __restrict__ rev)
{
    extern __shared__ float sm[];
    float* Xs=sm; float* Ws=sm+8320; float* bs=Ws+4352;
    __shared__ int srcs[128], revs[128];
    int tid=threadIdx.x, w=tid>>5, lane=tid&31;
    size_t base=(size_t)blockIdx.x*128;
    srcs[tid]=src[base+tid]; revs[tid]=rev[base+tid];
    for (int i=tid;i<4096;i+=128) Ws[(i>>6)*68+(i&63)]=W[i];
    if (tid<64) bs[tid]=b[tid];
    __syncthreads();
    for (int i=tid;i<8192;i+=128){
        int e=i>>6, f=i&63;
        Xs[e*65+f] = __ldg(&g_agg[(size_t)srcs[e]*64+f]) - __ldg(&g_m[(size_t)revs[e]*64+f]);
    }
    __syncthreads();
    u64 acc[4][8];
    gemm_core<4>(Xs,Ws,bs,w,lane,acc);
    __syncthreads();
    acc_to_os<4>(Xs,w,lane,acc);
    __syncthreads();
    for (int i=tid;i<8192;i+=128) g_x[base*64+i]=fmaxf(Xs[(i>>6)*65+(i&63)],0.f);
}

// ---------------- fused gates + GRU (persistent, all weights resident) ----------------
// smem: Xs[8320] Hs[8320] Wall[6*4352] Zs[32*256] bsm[256]
__global__ void __launch_bounds__(256) k_grufuse(
    const float* __restrict__ Wih, const float* __restrict__ bih,
    const float* __restrict__ Whh, const float* __restrict__ bhh)
{
    extern __shared__ float sm[];
    float* Xs  = sm;
    float* Hs  = sm + 8320;
    float* Wall= sm + 16640;
    float* Zs  = sm + 42752;
    float* bsm = sm + 50944;
    int tid=threadIdx.x, w=tid>>5, lane=tid&31;
    const int c0 = w*8;

    // load 6 transposed weight images once: Wall[m][k*68+c] = W[(g*64+c)*64+k]
    for (int i=tid;i<24576;i+=256){
        int m=i>>12, r=i&4095, c=r>>6, k=r&63;
        const float* Wsrc = (m<3)? Wih : Whh;
        int g = (m<3)? m : (m-3);
        Wall[m*4352 + k*68 + c] = Wsrc[(size_t)(g*64+c)*64 + k];
    }
    if (tid<64){
        bsm[tid]     = bih[tid]     + bhh[tid];       // r
        bsm[64+tid]  = bih[64+tid]  + bhh[64+tid];    // z
        bsm[128+tid] = bih[128+tid];                  // in
        bsm[192+tid] = bhh[128+tid];                  // hn
    }
    __syncthreads();

    for (int t=blockIdx.x; t<GRU_TILES; t+=gridDim.x){
        size_t base=(size_t)t*128;
        for (int i=tid;i<8192;i+=256){
            int e=i>>6, f=i&63;
            Xs[e*65+f]=__ldg(&g_x[base*64+i]);
            Hs[e*65+f]=__ldg(&g_message[base*64+i]);
        }
        __syncthreads();

        u64 acc[4][4];
        float rr[32];
        // pass r
        #pragma unroll
        for (int j=0;j<4;j++)
            #pragma unroll
            for (int q=0;q<4;q++) acc[j][q]=pack2(bsm[c0+2*q],bsm[c0+2*q+1]);
        gemm8(Xs, Wall+0*4352, c0, lane, acc);
        gemm8(Hs, Wall+3*4352, c0, lane, acc);
        #pragma unroll
        for (int j=0;j<4;j++)
            #pragma unroll
            for (int q=0;q<4;q++){
                float2 v=unpack2(acc[j][q]);
                rr[j*8+2*q]=sigf(v.x); rr[j*8+2*q+1]=sigf(v.y);
            }
        // pass z -> smem (same-thread slots)
        #pragma unroll
        for (int j=0;j<4;j++)
            #pragma unroll
            for (int q=0;q<4;q++) acc[j][q]=pack2(bsm[64+c0+2*q],bsm[64+c0+2*q+1]);
        gemm8(Xs, Wall+1*4352, c0, lane, acc);
        gemm8(Hs, Wall+4*4352, c0, lane, acc);
        #pragma unroll
        for (int j=0;j<4;j++)
            #pragma unroll
            for (int q=0;q<4;q++){
                float2 v=unpack2(acc[j][q]);
                Zs[(j*8+2*q)*256+tid]  =sigf(v.x);
                Zs[(j*8+2*q+1)*256+tid]=sigf(v.y);
            }
        // pass n (two accumulator sets)
        u64 accI[4][4], accH[4][4];
        #pragma unroll
        for (int j=0;j<4;j++)
            #pragma unroll
            for (int q=0;q<4;q++){
                accI[j][q]=pack2(bsm[128+c0+2*q],bsm[128+c0+2*q+1]);
                accH[j][q]=pack2(bsm[192+c0+2*q],bsm[192+c0+2*q+1]);
            }
        gemm8(Xs, Wall+2*4352, c0, lane, accI);
        gemm8(Hs, Wall+5*4352, c0, lane, accH);
        // combine GRU into registers (accI reused to hold outputs) — no smem writes yet
        #pragma unroll
        for (int j=0;j<4;j++){
            int e=lane+32*j;
            #pragma unroll
            for (int q=0;q<4;q++){
                float2 iv=unpack2(accI[j][q]);
                float2 hv=unpack2(accH[j][q]);
                int cA=c0+2*q, cB=cA+1;
                float nA=tanhf(iv.x + rr[j*8+2*q]  *hv.x);
                float nB=tanhf(iv.y + rr[j*8+2*q+1]*hv.y);
                float zA=Zs[(j*8+2*q)*256+tid],  zB=Zs[(j*8+2*q+1)*256+tid];
                float hA=Hs[e*65+cA], hB=Hs[e*65+cB];
                accI[j][q]=pack2((1.f-zA)*nA+zA*hA, (1.f-zB)*nB+zB*hB);
            }
        }
        __syncthreads();   // ALL gemm8/combine reads of Xs/Hs complete before any write
        #pragma unroll
        for (int j=0;j<4;j++){
            int e=lane+32*j;
            #pragma unroll
            for (int q=0;q<4;q++){
                float2 o=unpack2(accI[j][q]);
                Hs[e*65+c0+2*q]  =o.x;
                Hs[e*65+c0+2*q+1]=o.y;
            }
        }
        __syncthreads();
        for (int i=tid;i<8192;i+=256) g_message[base*64+i]=Hs[(i>>6)*65+(i&63)];
        __syncthreads();
    }
}

// ---------------- nodes_out ----------------
__global__ void __launch_bounds__(256) k_nodes_out(
    int iter, float* __restrict__ outM, float* __restrict__ outD,
    const float* __restrict__ Wagg, const float* __restrict__ bagg,
    const float* __restrict__ Wout)
{
    __shared__ float Wa[4096]; __shared__ float ba[64]; __shared__ float Wo[192];
    int tid=threadIdx.x;
    for (int i=tid;i<4096;i+=256) Wa[i]=Wagg[i];
    if (tid<64) ba[tid]=bagg[tid];
    for (int i=tid;i<192;i+=256) Wo[i]=Wout[i];
    __syncthreads();
    int n=blockIdx.x*256+tid;
    if (n>=NN) return;
    float af[64];
    const float4* ar=(const float4*)&g_agg[(size_t)n*64];
    #pragma unroll
    for (int q=0;q<16;q++){ float4 v=ar[q]; af[4*q]=v.x; af[4*q+1]=v.y; af[4*q+2]=v.z; af[4*q+3]=v.w; }
    u64 acc[32];
    #pragma unroll
    for (int j=0;j<32;j++) acc[j]=pack2(ba[2*j],ba[2*j+1]);
    #pragma unroll 4
    for (int k=0;k<64;k++){
        u64 x2=pack2(af[k],af[k]);
        const ulonglong2* wr=(const ulonglong2*)&Wa[k*64];
        #pragma unroll
        for (int q=0;q<16;q++){ ulonglong2 w=wr[q]; fma2(acc[2*q],x2,w.x); fma2(acc[2*q+1],x2,w.y); }
    }
    float l0=0.f,l1=0.f,l2=0.f;
    #pragma unroll
    for (int j=0;j<32;j++){
        float2 v=unpack2(acc[j]);
        float a0=fmaxf(v.x,0.f), a1=fmaxf(v.y,0.f);
        int k0=2*j, k1=2*j+1;
        l0 += a0*Wo[k0*3+0] + a1*Wo[k1*3+0];
        l1 += a0*Wo[k0*3+1] + a1*Wo[k1*3+1];
        l2 += a0*Wo[k0*3+2] + a1*Wo[k1*3+2];
    }
    l0=fmaxf(l0+g_nf_logit[n*3+0],0.f);
    l1=fmaxf(l1+g_nf_logit[n*3+1],0.f);
    l2=fmaxf(l2+g_nf_logit[n*3+2],0.f);
    float mx=fmaxf(l0,fmaxf(l1,l2));
    float e0=expf(l0-mx), e1=expf(l1-mx), e2=expf(l2-mx);
    float sum=e0+e1+e2, ls=logf(sum);
    size_t ob=(size_t)iter*((size_t)NN*3)+(size_t)n*3;
    outM[ob+0]=l0-mx-ls; outM[ob+1]=l1-mx-ls; outM[ob+2]=l2-mx-ls;
    float p2=e2/sum;
    if (iter>0){
        float d=fabsf(p2-g_prevp[n]);
        atomicMax((int*)&outD[iter-1], __float_as_int(d));
    }
    g_prevp[n]=p2;
}

// ---------------- host ----------------
extern "C" void kernel_launch(void* const* d_in, const int* in_sizes, int n_in,
                              void* d_out, int out_size)
{
    const int*   src  = (const int*)  d_in[0];
    const int*   tgt  = (const int*)  d_in[1];
    const int*   rev  = (const int*)  d_in[2];
    const float* raw  = (const float*)d_in[3];
    const float* prob = (const float*)d_in[4];
    const float* seed = (const float*)d_in[5];
    const float* W_node=(const float*)d_in[6],  *b_node=(const float*)d_in[7];
    const float* W_edge=(const float*)d_in[8],  *b_edge=(const float*)d_in[9];
    const float* W_init=(const float*)d_in[10], *b_init=(const float*)d_in[11];
    const float* W_aggr=(const float*)d_in[12], *b_aggr=(const float*)d_in[13];
    const float* W_out =(const float*)d_in[14], *b_out =(const float*)d_in[15];
    const float* W_me  =(const float*)d_in[16], *b_me  =(const float*)d_in[17];
    const float* W_mp  =(const float*)d_in[18], *b_mp  =(const float*)d_in[19];
    const float* W_ih  =(const float*)d_in[20], *W_hh  =(const float*)d_in[21];
    const float* b_ih  =(const float*)d_in[22], *b_hh  =(const float*)d_in[23];

    float* outM = (float*)d_out;
    float* outD = (float*)d_out + (size_t)5*NN*3;

    cudaFuncSetAttribute(k_edge_init, cudaFuncAttributeMaxDynamicSharedMemorySize, DSM);
    cudaFuncSetAttribute(k_me,        cudaFuncAttributeMaxDynamicSharedMemorySize, DSM);
    cudaFuncSetAttribute(k_mp,        cudaFuncAttributeMaxDynamicSharedMemorySize, DSM);
    cudaFuncSetAttribute(k_grufuse,   cudaFuncAttributeMaxDynamicSharedMemorySize, DSM_GRU);

    void *degPtr=0, *msgPtr=0, *mPtr=0;
    cudaGetSymbolAddress(&degPtr, g_deg);
    cudaGetSymbolAddress(&msgPtr, g_message);
    cudaGetSymbolAddress(&mPtr,   g_m);

    cudaMemsetAsync(degPtr, 0, NN*sizeof(int));
    cudaMemsetAsync(outD, 0, 4*sizeof(float));

    k_hist<<<EE/256,256>>>(tgt);
    k_scan<<<1,1024>>>();
    k_fill<<<EE/256,256>>>(tgt);
    k_node<<<(NN+255)/256,256>>>(prob, seed, W_node, b_node, W_init, b_init, W_out, b_out);
    k_edge_init<<<EE/128,128,DSM>>>(raw, src, W_edge, b_edge, W_init, W_me);

    k_gather<<<NN/4,256>>>((const float*)msgPtr);
    k_nodes_out<<<(NN+255)/256,256>>>(0, outM, outD, W_aggr, b_aggr, W_out);

    for (int l=0; l<4; l++){
        k_me<<<EE/128,128,DSM>>>(W_me, b_me);
        k_gather<<<NN/4,256>>>((const float*)mPtr);
        k_mp<<<EE/128,128,DSM>>>(W_mp, b_mp, src, rev);
        k_grufuse<<<GRU_GRID,256,DSM_GRU>>>(W_ih, b_ih, W_hh, b_hh);
        k_gather<<<NN/4,256>>>((const float*)msgPtr);
        k_nodes_out<<<(NN+255)/256,256>>>(l+1, outM, outD, W_aggr, b_aggr, W_out);
    }
}

// round 11
// speedup vs baseline: 2.0146x; 1.0815x over previous
#include <cuda_runtime.h>

#define NN 50000
#define EE 800000

typedef unsigned long long u64;

// ---------------- f32x2 helpers ----------------
__device__ __forceinline__ void fma2(u64 &c, u64 a, u64 b){
    asm("fma.rn.f32x2 %0, %1, %2, %0;" : "+l"(c) : "l"(a), "l"(b));
}
__device__ __forceinline__ u64 pack2(float x, float y){
    u64 r; asm("mov.b64 %0, {%1, %2};" : "=l"(r) : "f"(x), "f"(y)); return r;
}
__device__ __forceinline__ float2 unpack2(u64 v){
    float2 r; asm("mov.b64 {%0, %1}, %2;" : "=f"(r.x), "=f"(r.y) : "l"(v)); return r;
}
__device__ __forceinline__ float sigf(float x){ return 1.f/(1.f+__expf(-x)); }

// ---------------- scratch ----------------
__device__ float g_node_pre[(size_t)NN*64];
__device__ float g_nf_logit[(size_t)NN*3];
__device__ float g_prevp[NN];
__device__ float g_agg[(size_t)NN*64];
__device__ float g_contrib[(size_t)EE*64];
__device__ float g_message[(size_t)EE*64];
__device__ float g_m[(size_t)EE*64];
__device__ float g_x[(size_t)EE*64];
__device__ int   g_deg[NN];
__device__ int   g_rowptr[NN+1];
__device__ int   g_cursor[NN];
__device__ int   g_eid[EE];

#define DSM 50944            // gemm kernels: Xs 8320 + Ws 4352 + bs 64 floats
#define DSM_GRU 204800       // fused gru: Xs 8320 + Hs 8320 + W 26112 + Zs 8192 + b 256 floats
#define GRU_GRID 152
#define GRU_TILES 6250       // EE/128

// ---------------- GEMM core: TE=128; warp w -> cols 16w..; lane -> edges lane+32j ----------------
template<int NJ>
__device__ __forceinline__ void gemm_core(const float* Xs, const float* Ws, const float* bs,
                                          int w, int lane, u64 (&acc)[NJ][8])
{
    const int c0 = w*16;
    #pragma unroll
    for (int j=0;j<NJ;j++)
        #pragma unroll
        for (int q=0;q<8;q++) acc[j][q]=pack2(bs[c0+2*q],bs[c0+2*q+1]);
    #pragma unroll 2
    for (int k=0;k<64;k++){
        const ulonglong2* wp=(const ulonglong2*)(Ws + k*68 + c0);
        ulonglong2 a0=wp[0],a1=wp[1],a2=wp[2],a3=wp[3];
        u64 w8[8]={a0.x,a0.y,a1.x,a1.y,a2.x,a2.y,a3.x,a3.y};
        #pragma unroll
        for (int j=0;j<NJ;j++){
            float xk = Xs[(lane+32*j)*65 + k];
            u64 x2 = pack2(xk,xk);
            #pragma unroll
            for (int q=0;q<8;q++) fma2(acc[j][q],x2,w8[q]);
        }
    }
}
template<int NJ>
__device__ __forceinline__ void acc_to_os(float* Os,int w,int lane,u64 (&acc)[NJ][8]){
    const int c0=w*16;
    #pragma unroll
    for (int j=0;j<NJ;j++){
        float* row=&Os[(lane+32*j)*65 + c0];
        #pragma unroll
        for (int q=0;q<8;q++){ float2 v=unpack2(acc[j][q]); row[2*q]=v.x; row[2*q+1]=v.y; }
    }
}

// ---------------- 8-col x 2-edge GEMM core for fused GRU (512-thread version) ----------------
__device__ __forceinline__ void gemm8x2(const float* Xs, const float* Wm, int c0, int e0,
                                        u64 (&acc)[2][4])
{
    #pragma unroll 4
    for (int k=0;k<64;k++){
        const ulonglong2* wp=(const ulonglong2*)(Wm + k*68 + c0);
        ulonglong2 a0=wp[0], a1=wp[1];
        u64 w4[4]={a0.x,a0.y,a1.x,a1.y};
        #pragma unroll
        for (int j=0;j<2;j++){
            float xk = Xs[(e0+32*j)*65 + k];
            u64 x2 = pack2(xk,xk);
            #pragma unroll
            for (int q=0;q<4;q++) fma2(acc[j][q],x2,w4[q]);
        }
    }
}

// ---------------- CSR build ----------------
__global__ void __launch_bounds__(256) k_hist(const int* __restrict__ tgt){
    int e=blockIdx.x*256+threadIdx.x;
    atomicAdd(&g_deg[tgt[e]],1);
}
__global__ void __launch_bounds__(1024) k_scan(){
    __shared__ int wsum[32];
    __shared__ int carry_s;
    int t=threadIdx.x, lane=t&31, wid=t>>5;
    if (t==0){ g_rowptr[0]=0; carry_s=0; }
    __syncthreads();
    for (int base=0; base<NN; base+=1024){
        int i=base+t;
        int v=(i<NN)? g_deg[i] : 0;
        int s=v;
        #pragma unroll
        for (int o=1;o<32;o<<=1){ int u=__shfl_up_sync(0xffffffffu,s,o); if(lane>=o) s+=u; }
        if (lane==31) wsum[wid]=s;
        __syncthreads();
        if (wid==0){
            int ws=wsum[lane];
            #pragma unroll
            for (int o=1;o<32;o<<=1){ int u=__shfl_up_sync(0xffffffffu,ws,o); if(lane>=o) ws+=u; }
            wsum[lane]=ws;
        }
        __syncthreads();
        int off=(wid>0)? wsum[wid-1] : 0;
        int inc=s+off+carry_s;
        if (i<NN){ g_rowptr[i+1]=inc; g_cursor[i]=inc-v; }
        __syncthreads();
        if (t==1023) carry_s=inc;
        __syncthreads();
    }
}
__global__ void __launch_bounds__(256) k_fill(const int* __restrict__ tgt){
    int e=blockIdx.x*256+threadIdx.x;
    int p=atomicAdd(&g_cursor[tgt[e]],1);
    g_eid[p]=e;
}

// ---------------- segment sum by gather ----------------
__global__ void __launch_bounds__(256) k_gather(const float* __restrict__ S){
    int node=blockIdx.x*4+(threadIdx.x>>6);
    int f=threadIdx.x&63;
    int s=g_rowptr[node], e=g_rowptr[node+1];
    float a=0.f;
    for (int i=s;i<e;i++){
        int eid=__ldg(&g_eid[i]);
        a += __ldg(&S[(size_t)eid*64+f]);
    }
    g_agg[(size_t)node*64+f]=a;
}

// ---------------- per-node precompute ----------------
__global__ void __launch_bounds__(256) k_node(
    const float* __restrict__ prob, const float* __restrict__ seed,
    const float* __restrict__ W_node, const float* __restrict__ b_node,
    const float* __restrict__ W_init, const float* __restrict__ b_init,
    const float* __restrict__ W_out,  const float* __restrict__ b_out)
{
    __shared__ float Wi[4096];
    __shared__ float Wn0[64], Wn1[64], bn[64], bi[64], Wo[192], bo[3];
    int tid = threadIdx.x;
    for (int i=tid;i<4096;i+=256) Wi[i]=W_init[i];
    if (tid<64){ Wn0[tid]=W_node[tid]; Wn1[tid]=W_node[64+tid]; bn[tid]=b_node[tid]; bi[tid]=b_init[tid]; }
    for (int i=tid;i<192;i+=256) Wo[i]=W_out[192+i];
    if (tid<3) bo[tid]=b_out[tid];
    __syncthreads();
    int n = blockIdx.x*256 + tid;
    if (n >= NN) return;
    float p = prob[n], s = seed[n];
    u64 acc[32];
    #pragma unroll
    for (int j=0;j<32;j++) acc[j]=pack2(bi[2*j],bi[2*j+1]);
    float l0=bo[0], l1=bo[1], l2=bo[2];
    #pragma unroll 4
    for (int k=0;k<64;k++){
        float nf = fmaxf(fmaf(p,Wn0[k],fmaf(s,Wn1[k],bn[k])), 0.f);
        u64 x2 = pack2(nf,nf);
        const ulonglong2* wr = (const ulonglong2*)&Wi[k*64];
        #pragma unroll
        for (int q=0;q<16;q++){ ulonglong2 w=wr[q]; fma2(acc[2*q],x2,w.x); fma2(acc[2*q+1],x2,w.y); }
        l0 = fmaf(nf,Wo[k*3],l0); l1 = fmaf(nf,Wo[k*3+1],l1); l2 = fmaf(nf,Wo[k*3+2],l2);
    }
    float4* outp = (float4*)&g_node_pre[(size_t)n*64];
    #pragma unroll
    for (int q=0;q<16;q++){ float2 a=unpack2(acc[2*q]); float2 b=unpack2(acc[2*q+1]); outp[q]=make_float4(a.x,a.y,b.x,b.y); }
    g_nf_logit[n*3]=l0; g_nf_logit[n*3+1]=l1; g_nf_logit[n*3+2]=l2;
}

// ---------------- edge init (TE=128, NJ=4) ----------------
__global__ void __launch_bounds__(128,3) k_edge_init(
    const float* __restrict__ raw, const int* __restrict__ src,
    const float* __restrict__ W_edge, const float* __restrict__ b_edge,
    const float* __restrict__ W_init, const float* __restrict__ W_me)
{
    extern __shared__ float sm[];
    float* Xs=sm; float* Ws=sm+8320; float* bs=Ws+4352;
    __shared__ float we[64], be[64], rawv[128];
    __shared__ int srcs[128];
    int tid=threadIdx.x, w=tid>>5, lane=tid&31;
    size_t base=(size_t)blockIdx.x*128;
    if (tid<64){ we[tid]=W_edge[tid]; be[tid]=b_edge[tid]; bs[tid]=0.f; }
    rawv[tid]=raw[base+tid]; srcs[tid]=src[base+tid];
    for (int i=tid;i<4096;i+=128) Ws[(i>>6)*68+(i&63)]=W_init[4096+i];
    __syncthreads();
    for (int i=tid;i<8192;i+=128){ int e=i>>6,f=i&63; Xs[e*65+f]=fmaxf(fmaf(rawv[e],we[f],be[f]),0.f); }
    __syncthreads();
    u64 acc[4][8];
    gemm_core<4>(Xs,Ws,bs,w,lane,acc);
    __syncthreads();
    acc_to_os<4>(Xs,w,lane,acc);
    __syncthreads();
    for (int i=tid;i<8192;i+=128){
        int e=i>>6, f=i&63;
        float v=Xs[e*65+f] + __ldg(&g_node_pre[(size_t)srcs[e]*64+f]);
        g_message[base*64+i]=fmaxf(v,0.f);
    }
    __syncthreads();
    for (int i=tid;i<4096;i+=128) Ws[(i>>6)*68+(i&63)]=W_me[4096+i];
    __syncthreads();
    for (int i=tid;i<8192;i+=128){ int e=i>>6,f=i&63; Xs[e*65+f]=fmaxf(fmaf(rawv[e],we[f],be[f]),0.f); }
    __syncthreads();
    gemm_core<4>(Xs,Ws,bs,w,lane,acc);
    __syncthreads();
    acc_to_os<4>(Xs,w,lane,acc);
    __syncthreads();
    for (int i=tid;i<8192;i+=128) g_contrib[base*64+i]=Xs[(i>>6)*65+(i&63)];
}

// ---------------- m = relu(message @ W_me[0:64] + contrib + b_me) ----------------
__global__ void __launch_bounds__(128,3) k_me(const float* __restrict__ W, const float* __restrict__ b)
{
    extern __shared__ float sm[];
    float* Xs=sm; float* Ws=sm+8320; float* bs=Ws+4352;
    int tid=threadIdx.x, w=tid>>5, lane=tid&31;
    size_t base=(size_t)blockIdx.x*128;
    for (int i=tid;i<4096;i+=128) Ws[(i>>6)*68+(i&63)]=W[i];
    if (tid<64) bs[tid]=b[tid];
    for (int i=tid;i<8192;i+=128) Xs[(i>>6)*65+(i&63)]=g_message[base*64+i];
    __syncthreads();
    u64 acc[4][8];
    gemm_core<4>(Xs,Ws,bs,w,lane,acc);
    __syncthreads();
    acc_to_os<4>(Xs,w,lane,acc);
    __syncthreads();
    for (int i=tid;i<8192;i+=128){
        float v=Xs[(i>>6)*65+(i&63)] + g_contrib[base*64+i];
        g_m[base*64+i]=fmaxf(v,0.f);
    }
}

// ---------------- x = relu((agg[src] - m[rev]) @ W_mp + b_mp) ----------------
__global__ void __launch_bounds__(128,3) k_mp(
    const float* __restrict__ W, const float* __restrict__ b,
    const int* __restrict__ src, const int* __restrict__ rev)
{
    extern __shared__ float sm[];
    float* Xs=sm; float* Ws=sm+8320; float* bs=Ws+4352;
    __shared__ int srcs[128], revs[128];
    int tid=threadIdx.x, w=tid>>5, lane=tid&31;
    size_t base=(size_t)blockIdx.x*128;
    srcs[tid]=src[base+tid]; revs[tid]=rev[base+tid];
    for (int i=tid;i<4096;i+=128) Ws[(i>>6)*68+(i&63)]=W[i];
    if (tid<64) bs[tid]=b[tid];
    __syncthreads();
    for (int i=tid;i<8192;i+=128){
        int e=i>>6, f=i&63;
        Xs[e*65+f] = __ldg(&g_agg[(size_t)srcs[e]*64+f]) - __ldg(&g_m[(size_t)revs[e]*64+f]);
    }
    __syncthreads();
    u64 acc[4][8];
    gemm_core<4>(Xs,Ws,bs,w,lane,acc);
    __syncthreads();
    acc_to_os<4>(Xs,w,lane,acc);
    __syncthreads();
    for (int i=tid;i<8192;i+=128) g_x[base*64+i]=fmaxf(Xs[(i>>6)*65+(i&63)],0.f);
}

// ---------------- fused gates + GRU (persistent, 512 threads, weights resident) ----------------
// smem: Xs[8320] Hs[8320] Wall[6*4352] Zs[16*512] bsm[256]
// warp w (0..15): col group c0=(w&7)*8, edge half eh=(w>>3)*64; thread -> 2 edges x 8 cols
__global__ void __launch_bounds__(512,1) k_grufuse(
    const float* __restrict__ Wih, const float* __restrict__ bih,
    const float* __restrict__ Whh, const float* __restrict__ bhh)
{
    extern __shared__ float sm[];
    float* Xs  = sm;
    float* Hs  = sm + 8320;
    float* Wall= sm + 16640;
    float* Zs  = sm + 42752;
    float* bsm = sm + 50944;
    int tid=threadIdx.x, w=tid>>5, lane=tid&31;
    const int c0 = (w&7)*8;
    const int e0 = (w>>3)*64 + lane;   // edges e0, e0+32

    // load 6 transposed weight images once: Wall[m][k*68+c] = W[(g*64+c)*64+k]
    for (int i=tid;i<24576;i+=512){
        int m=i>>12, r=i&4095, c=r>>6, k=r&63;
        const float* Wsrc = (m<3)? Wih : Whh;
        int g = (m<3)? m : (m-3);
        Wall[m*4352 + k*68 + c] = Wsrc[(size_t)(g*64+c)*64 + k];
    }
    if (tid<64){
        bsm[tid]     = bih[tid]     + bhh[tid];       // r
        bsm[64+tid]  = bih[64+tid]  + bhh[64+tid];    // z
        bsm[128+tid] = bih[128+tid];                  // in
        bsm[192+tid] = bhh[128+tid];                  // hn
    }
    __syncthreads();

    for (int t=blockIdx.x; t<GRU_TILES; t+=gridDim.x){
        size_t base=(size_t)t*128;
        for (int i=tid;i<8192;i+=512){
            int e=i>>6, f=i&63;
            Xs[e*65+f]=__ldg(&g_x[base*64+i]);
            Hs[e*65+f]=__ldg(&g_message[base*64+i]);
        }
        __syncthreads();

        u64 acc[2][4];
        float rr[16];
        // pass r
        #pragma unroll
        for (int j=0;j<2;j++)
            #pragma unroll
            for (int q=0;q<4;q++) acc[j][q]=pack2(bsm[c0+2*q],bsm[c0+2*q+1]);
        gemm8x2(Xs, Wall+0*4352, c0, e0, acc);
        gemm8x2(Hs, Wall+3*4352, c0, e0, acc);
        #pragma unroll
        for (int j=0;j<2;j++)
            #pragma unroll
            for (int q=0;q<4;q++){
                float2 v=unpack2(acc[j][q]);
                rr[j*8+2*q]=sigf(v.x); rr[j*8+2*q+1]=sigf(v.y);
            }
        // pass z -> smem (same-thread slots)
        #pragma unroll
        for (int j=0;j<2;j++)
            #pragma unroll
            for (int q=0;q<4;q++) acc[j][q]=pack2(bsm[64+c0+2*q],bsm[64+c0+2*q+1]);
        gemm8x2(Xs, Wall+1*4352, c0, e0, acc);
        gemm8x2(Hs, Wall+4*4352, c0, e0, acc);
        #pragma unroll
        for (int j=0;j<2;j++)
            #pragma unroll
            for (int q=0;q<4;q++){
                float2 v=unpack2(acc[j][q]);
                Zs[(j*8+2*q)*512+tid]  =sigf(v.x);
                Zs[(j*8+2*q+1)*512+tid]=sigf(v.y);
            }
        // pass n (two accumulator sets)
        u64 accI[2][4], accH[2][4];
        #pragma unroll
        for (int j=0;j<2;j++)
            #pragma unroll
            for (int q=0;q<4;q++){
                accI[j][q]=pack2(bsm[128+c0+2*q],bsm[128+c0+2*q+1]);
                accH[j][q]=pack2(bsm[192+c0+2*q],bsm[192+c0+2*q+1]);
            }
        gemm8x2(Xs, Wall+2*4352, c0, e0, accI);
        gemm8x2(Hs, Wall+5*4352, c0, e0, accH);
        // combine GRU into registers — no smem writes yet
        #pragma unroll
        for (int j=0;j<2;j++){
            int e=e0+32*j;
            #pragma unroll
            for (int q=0;q<4;q++){
                float2 iv=unpack2(accI[j][q]);
                float2 hv=unpack2(accH[j][q]);
                int cA=c0+2*q, cB=cA+1;
                float nA=tanhf(iv.x + rr[j*8+2*q]  *hv.x);
                float nB=tanhf(iv.y + rr[j*8+2*q+1]*hv.y);
                float zA=Zs[(j*8+2*q)*512+tid],  zB=Zs[(j*8+2*q+1)*512+tid];
                float hA=Hs[e*65+cA], hB=Hs[e*65+cB];
                accI[j][q]=pack2((1.f-zA)*nA+zA*hA, (1.f-zB)*nB+zB*hB);
            }
        }
        __syncthreads();   // ALL reads of Xs/Hs complete before any write
        #pragma unroll
        for (int j=0;j<2;j++){
            int e=e0+32*j;
            #pragma unroll
            for (int q=0;q<4;q++){
                float2 o=unpack2(accI[j][q]);
                Hs[e*65+c0+2*q]  =o.x;
                Hs[e*65+c0+2*q+1]=o.y;
            }
        }
        __syncthreads();
        for (int i=tid;i<8192;i+=512) g_message[base*64+i]=Hs[(i>>6)*65+(i&63)];
        __syncthreads();
    }
}

// ---------------- nodes_out ----------------
__global__ void __launch_bounds__(256) k_nodes_out(
    int iter, float* __restrict__ outM, float* __restrict__ outD,
    const float* __restrict__ Wagg, const float* __restrict__ bagg,
    const float* __restrict__ Wout)
{
    __shared__ float Wa[4096]; __shared__ float ba[64]; __shared__ float Wo[192];
    int tid=threadIdx.x;
    for (int i=tid;i<4096;i+=256) Wa[i]=Wagg[i];
    if (tid<64) ba[tid]=bagg[tid];
    for (int i=tid;i<192;i+=256) Wo[i]=Wout[i];
    __syncthreads();
    int n=blockIdx.x*256+tid;
    if (n>=NN) return;
    float af[64];
    const float4* ar=(const float4*)&g_agg[(size_t)n*64];
    #pragma unroll
    for (int q=0;q<16;q++){ float4 v=ar[q]; af[4*q]=v.x; af[4*q+1]=v.y; af[4*q+2]=v.z; af[4*q+3]=v.w; }
    u64 acc[32];
    #pragma unroll
    for (int j=0;j<32;j++) acc[j]=pack2(ba[2*j],ba[2*j+1]);
    #pragma unroll 4
    for (int k=0;k<64;k++){
        u64 x2=pack2(af[k],af[k]);
        const ulonglong2* wr=(const ulonglong2*)&Wa[k*64];
        #pragma unroll
        for (int q=0;q<16;q++){ ulonglong2 w=wr[q]; fma2(acc[2*q],x2,w.x); fma2(acc[2*q+1],x2,w.y); }
    }
    float l0=0.f,l1=0.f,l2=0.f;
    #pragma unroll
    for (int j=0;j<32;j++){
        float2 v=unpack2(acc[j]);
        float a0=fmaxf(v.x,0.f), a1=fmaxf(v.y,0.f);
        int k0=2*j, k1=2*j+1;
        l0 += a0*Wo[k0*3+0] + a1*Wo[k1*3+0];
        l1 += a0*Wo[k0*3+1] + a1*Wo[k1*3+1];
        l2 += a0*Wo[k0*3+2] + a1*Wo[k1*3+2];
    }
    l0=fmaxf(l0+g_nf_logit[n*3+0],0.f);
    l1=fmaxf(l1+g_nf_logit[n*3+1],0.f);
    l2=fmaxf(l2+g_nf_logit[n*3+2],0.f);
    float mx=fmaxf(l0,fmaxf(l1,l2));
    float e0=expf(l0-mx), e1=expf(l1-mx), e2=expf(l2-mx);
    float sum=e0+e1+e2, ls=logf(sum);
    size_t ob=(size_t)iter*((size_t)NN*3)+(size_t)n*3;
    outM[ob+0]=l0-mx-ls; outM[ob+1]=l1-mx-ls; outM[ob+2]=l2-mx-ls;
    float p2=e2/sum;
    if (iter>0){
        float d=fabsf(p2-g_prevp[n]);
        atomicMax((int*)&outD[iter-1], __float_as_int(d));
    }
    g_prevp[n]=p2;
}

// ---------------- host ----------------
extern "C" void kernel_launch(void* const* d_in, const int* in_sizes, int n_in,
                              void* d_out, int out_size)
{
    const int*   src  = (const int*)  d_in[0];
    const int*   tgt  = (const int*)  d_in[1];
    const int*   rev  = (const int*)  d_in[2];
    const float* raw  = (const float*)d_in[3];
    const float* prob = (const float*)d_in[4];
    const float* seed = (const float*)d_in[5];
    const float* W_node=(const float*)d_in[6],  *b_node=(const float*)d_in[7];
    const float* W_edge=(const float*)d_in[8],  *b_edge=(const float*)d_in[9];
    const float* W_init=(const float*)d_in[10], *b_init=(const float*)d_in[11];
    const float* W_aggr=(const float*)d_in[12], *b_aggr=(const float*)d_in[13];
    const float* W_out =(const float*)d_in[14], *b_out =(const float*)d_in[15];
    const float* W_me  =(const float*)d_in[16], *b_me  =(const float*)d_in[17];
    const float* W_mp  =(const float*)d_in[18], *b_mp  =(const float*)d_in[19];
    const float* W_ih  =(const float*)d_in[20], *W_hh  =(const float*)d_in[21];
    const float* b_ih  =(const float*)d_in[22], *b_hh  =(const float*)d_in[23];

    float* outM = (float*)d_out;
    float* outD = (float*)d_out + (size_t)5*NN*3;

    cudaFuncSetAttribute(k_edge_init, cudaFuncAttributeMaxDynamicSharedMemorySize, DSM);
    cudaFuncSetAttribute(k_me,        cudaFuncAttributeMaxDynamicSharedMemorySize, DSM);
    cudaFuncSetAttribute(k_mp,        cudaFuncAttributeMaxDynamicSharedMemorySize, DSM);
    cudaFuncSetAttribute(k_grufuse,   cudaFuncAttributeMaxDynamicSharedMemorySize, DSM_GRU);

    void *degPtr=0, *msgPtr=0, *mPtr=0;
    cudaGetSymbolAddress(&degPtr, g_deg);
    cudaGetSymbolAddress(&msgPtr, g_message);
    cudaGetSymbolAddress(&mPtr,   g_m);

    // launch order: #6 = k_edge_init (ncu -s 5 -c 1 captures it; memsets count)
    cudaMemsetAsync(degPtr, 0, NN*sizeof(int));                                             // 1
    cudaMemsetAsync(outD, 0, 4*sizeof(float));                                              // 2
    k_hist<<<EE/256,256>>>(tgt);                                                            // 3
    k_scan<<<1,1024>>>();                                                                   // 4
    k_node<<<(NN+255)/256,256>>>(prob, seed, W_node, b_node, W_init, b_init, W_out, b_out); // 5
    k_edge_init<<<EE/128,128,DSM>>>(raw, src, W_edge, b_edge, W_init, W_me);                // 6 (captured)
    k_fill<<<EE/256,256>>>(tgt);                                                            // 7

    k_gather<<<NN/4,256>>>((const float*)msgPtr);
    k_nodes_out<<<(NN+255)/256,256>>>(0, outM, outD, W_aggr, b_aggr, W_out);

    for (int l=0; l<4; l++){
        k_me<<<EE/128,128,DSM>>>(W_me, b_me);
        k_gather<<<NN/4,256>>>((const float*)mPtr);
        k_mp<<<EE/128,128,DSM>>>(W_mp, b_mp, src, rev);
        k_grufuse<<<GRU_GRID,512,DSM_GRU>>>(W_ih, b_ih, W_hh, b_hh);
        k_gather<<<NN/4,256>>>((const float*)msgPtr);
        k_nodes_out<<<(NN+255)/256,256>>>(l+1, outM, outD, W_aggr, b_aggr, W_out);
    }
}